// round 1
// baseline (speedup 1.0000x reference)
#include <cuda_runtime.h>
#include <math.h>

// Problem constants
#define BB   8
#define NN   20000
#define PP   256
#define SS   32
#define CC   256
#define NCC  18
#define BP   (BB*PP)      // 2048

// ---------------- scratch (no allocation allowed -> __device__ globals) -------------
__device__ int   g_sel[BP*SS];
__device__ float g_nf [BP*128];
__device__ float g_lf [BP*256];
__device__ float g_ss [BB*256];
__device__ float g_ss2[BB*512];

// transposed weights: layout [K][O] (wt[c*O + o])
__device__ __align__(16) float g_mw0t [259*128];
__device__ __align__(16) float g_mw1t [128*128];
__device__ __align__(16) float g_mw2t [128*128];
__device__ __align__(16) float g_lw0t [146*256];
__device__ __align__(16) float g_lw1t [256*256];
__device__ __align__(16) float g_lw2t [256*256];
__device__ __align__(16) float g_tw0t [128*512];
__device__ __align__(16) float g_tw1t [512*512];
__device__ __align__(16) float g_bwt  [512*256];
__device__ __align__(16) float g_tlw0t[256*1024];
__device__ __align__(16) float g_tlw1t[1024*1024];
__device__ __align__(16) float g_blwt [1024*512];

__device__ float* wt_ptr(int id) {
    switch (id) {
        case 0:  return g_mw0t;
        case 1:  return g_mw1t;
        case 2:  return g_mw2t;
        case 3:  return g_lw0t;
        case 4:  return g_lw1t;
        case 5:  return g_lw2t;
        case 6:  return g_tw0t;
        case 7:  return g_tw1t;
        case 8:  return g_bwt;
        case 9:  return g_tlw0t;
        case 10: return g_tlw1t;
        default: return g_blwt;
    }
}

// W[o*K + c] -> WT[c*O + o]; reads coalesced
__global__ void k_transpose(const float* __restrict__ src, int O, int K, int id) {
    float* dst = wt_ptr(id);
    int i = blockIdx.x * blockDim.x + threadIdx.x;
    if (i < O * K) {
        int o = i / K, c = i - o * K;
        dst[c * O + o] = src[i];
    }
}

// ---------------- kernel A: in-box sampling (warp per proposal, early exit) ---------
__global__ void k_sample(const float* __restrict__ xyz,
                         const float* __restrict__ bsize,
                         const int*   __restrict__ inds) {
    __shared__ int buf[8][SS];
    int lane = threadIdx.x & 31, w = threadIdx.x >> 5;
    int q = blockIdx.x * 8 + w;
    int b = q >> 8;
    int n0 = inds[q];
    const float* xb = xyz + (size_t)b * NN * 3;
    float cx = xb[n0*3+0], cy = xb[n0*3+1], cz = xb[n0*3+2];
    float hx = bsize[q*3+0]*0.5f, hy = bsize[q*3+1]*0.5f, hz = bsize[q*3+2]*0.5f;

    int found = 0;
    for (int base = 0; base < NN; base += 32) {   // NN = 625*32 exactly
        int n = base + lane;
        float px = xb[n*3+0], py = xb[n*3+1], pz = xb[n*3+2];
        bool in = (fabsf(px-cx) <= hx) && (fabsf(py-cy) <= hy) && (fabsf(pz-cz) <= hz);
        unsigned m = __ballot_sync(0xffffffffu, in);
        if (in) {
            int slot = found + __popc(m & ((1u << lane) - 1u));
            if (slot < SS) buf[w][slot] = n;
        }
        found += __popc(m);
        if (found >= SS) break;                    // warp-uniform
    }
    __syncwarp();
    int eff = found < SS ? found : SS;
    int sel = 0;
    if (eff > 0) sel = buf[w][lane % eff];        // cycle first-eff in order (matches argsort)
    g_sel[q*SS + lane] = sel;
}

// ---------------- kernel B: gather + 3-layer point MLP + maxpool --------------------
#define GST 263   // 263 % 32 = 7 -> conflict-free
#define HST 133   // 133 % 32 = 5 -> conflict-free

template<int K>
__device__ __forceinline__ void layer16(const float* __restrict__ in, int istride,
                                        const float* __restrict__ wt,
                                        const float* __restrict__ bias,
                                        float* __restrict__ out, int s, int og) {
    float acc[16];
    {
        const float4* b4 = reinterpret_cast<const float4*>(bias + og * 16);
        float4 t0 = b4[0], t1 = b4[1], t2 = b4[2], t3 = b4[3];
        acc[0]=t0.x; acc[1]=t0.y; acc[2]=t0.z; acc[3]=t0.w;
        acc[4]=t1.x; acc[5]=t1.y; acc[6]=t1.z; acc[7]=t1.w;
        acc[8]=t2.x; acc[9]=t2.y; acc[10]=t2.z; acc[11]=t2.w;
        acc[12]=t3.x; acc[13]=t3.y; acc[14]=t3.z; acc[15]=t3.w;
    }
    const float4* w4 = reinterpret_cast<const float4*>(wt) + og * 4;
    const float* inr = in + s * istride;
    #pragma unroll 4
    for (int c = 0; c < K; c++) {
        float gv = inr[c];
        float4 a0 = w4[c*32+0], a1 = w4[c*32+1], a2 = w4[c*32+2], a3 = w4[c*32+3];
        acc[0]  += gv * a0.x; acc[1]  += gv * a0.y; acc[2]  += gv * a0.z; acc[3]  += gv * a0.w;
        acc[4]  += gv * a1.x; acc[5]  += gv * a1.y; acc[6]  += gv * a1.z; acc[7]  += gv * a1.w;
        acc[8]  += gv * a2.x; acc[9]  += gv * a2.y; acc[10] += gv * a2.z; acc[11] += gv * a2.w;
        acc[12] += gv * a3.x; acc[13] += gv * a3.y; acc[14] += gv * a3.z; acc[15] += gv * a3.w;
    }
    float* o = out + s * HST + og * 16;
    #pragma unroll
    for (int j = 0; j < 16; j++) o[j] = fmaxf(acc[j], 0.0f);
}

__global__ void k_mlp(const float* __restrict__ xyz, const float* __restrict__ feat,
                      const int* __restrict__ inds,
                      const float* __restrict__ mb0, const float* __restrict__ mb1,
                      const float* __restrict__ mb2) {
    extern __shared__ float sm[];
    float* g  = sm;                    // [32][263]
    float* hA = sm + 32 * GST;         // [32][133]
    float* hB = hA + 32 * HST;         // [32][133]
    __shared__ int   sidx[SS];
    __shared__ float ctr[3];

    int q = blockIdx.x, b = q >> 8;
    int tid = threadIdx.x;             // 256 threads
    if (tid < SS) sidx[tid] = g_sel[q*SS + tid];
    if (tid == 0) {
        int n0 = inds[q];
        ctr[0] = xyz[((size_t)b*NN + n0)*3 + 0];
        ctr[1] = xyz[((size_t)b*NN + n0)*3 + 1];
        ctr[2] = xyz[((size_t)b*NN + n0)*3 + 2];
    }
    __syncthreads();

    const float* fb = feat + (size_t)b * CC * NN;
    for (int i = tid; i < SS * CC; i += 256) {
        int s = i >> 8, c = i & 255;
        g[s*GST + 3 + c] = fb[(size_t)c * NN + sidx[s]];
    }
    if (tid < SS * 3) {
        int s = tid / 3, d = tid - s * 3;
        g[s*GST + d] = xyz[((size_t)b*NN + sidx[s])*3 + d] - ctr[d];
    }
    __syncthreads();

    int s = tid & 31, og = tid >> 5;
    layer16<259>(g,  GST, g_mw0t, mb0, hA, s, og); __syncthreads();
    layer16<128>(hA, HST, g_mw1t, mb1, hB, s, og); __syncthreads();
    layer16<128>(hB, HST, g_mw2t, mb2, hA, s, og); __syncthreads();

    if (tid < 128) {
        float m = 0.0f;  // relu outputs are >= 0
        #pragma unroll
        for (int ss2 = 0; ss2 < SS; ss2++) m = fmaxf(m, hA[ss2*HST + tid]);
        g_nf[q*128 + tid] = m;
    }
}

// ---------------- kernel C: label MLP (146 -> 256 -> 256 -> 256) --------------------
__global__ void k_label(const float* __restrict__ blabel,
                        const float* __restrict__ lb0, const float* __restrict__ lb1,
                        const float* __restrict__ lb2) {
    __shared__ float in0[146];
    __shared__ float hA[256];
    __shared__ float hB[256];
    int q = blockIdx.x;
    int tid = threadIdx.x;            // 256 threads, tid == output channel
    if (tid < NCC) in0[tid] = blabel[q*NCC + tid];
    else if (tid < 146) in0[tid] = g_nf[q*128 + (tid - NCC)];
    __syncthreads();

    float acc = lb0[tid];
    #pragma unroll 2
    for (int c = 0; c < 146; c++) acc += in0[c] * g_lw0t[c*256 + tid];
    hA[tid] = fmaxf(acc, 0.0f);
    __syncthreads();

    acc = lb1[tid];
    #pragma unroll 4
    for (int c = 0; c < 256; c++) acc += hA[c] * g_lw1t[c*256 + tid];
    hB[tid] = fmaxf(acc, 0.0f);
    __syncthreads();

    acc = lb2[tid];
    #pragma unroll 4
    for (int c = 0; c < 256; c++) acc += hB[c] * g_lw2t[c*256 + tid];
    g_lf[q*256 + tid] = fmaxf(acc, 0.0f);
}

// ---------------- kernel E: time MLPs (per batch) -----------------------------------
__device__ __forceinline__ float gelu_exact(float x) {
    return 0.5f * x * (1.0f + erff(x * 0.70710678118654752f));
}
__device__ __forceinline__ float silu_f(float x) { return x / (1.0f + expf(-x)); }

__global__ void k_time(const float* __restrict__ ts,
                       const float* __restrict__ tb0, const float* __restrict__ tb1,
                       const float* __restrict__ bb_,
                       const float* __restrict__ tlb0, const float* __restrict__ tlb1,
                       const float* __restrict__ blb) {
    __shared__ float e1[128], e2[256], t1[512], s1[512], t2s[1024], s2[1024];
    int b = blockIdx.x, tid = threadIdx.x;  // 1024 threads
    float t = ts[b];
    if (tid < 64)  { float f = expf(tid * (-9.210340371976184f/63.0f));
                     float e = t*f; e1[tid] = sinf(e); e1[64+tid]  = cosf(e); }
    if (tid < 128) { float f = expf(tid * (-9.210340371976184f/127.0f));
                     float e = t*f; e2[tid] = sinf(e); e2[128+tid] = cosf(e); }
    __syncthreads();
    if (tid < 512) { float a = tb0[tid];
                     for (int c = 0; c < 128; c++) a += e1[c] * g_tw0t[c*512 + tid];
                     t1[tid] = gelu_exact(a); }
    { float a = tlb0[tid];
      for (int c = 0; c < 256; c++) a += e2[c] * g_tlw0t[c*1024 + tid];
      t2s[tid] = gelu_exact(a); }
    __syncthreads();
    if (tid < 512) { float a = tb1[tid];
                     for (int c = 0; c < 512; c++) a += t1[c] * g_tw1t[c*512 + tid];
                     s1[tid] = silu_f(a); }
    { float a = tlb1[tid];
      for (int c = 0; c < 1024; c++) a += t2s[c] * g_tlw1t[c*1024 + tid];
      s2[tid] = silu_f(a); }
    __syncthreads();
    if (tid < 256) { float a = bb_[tid];
                     for (int c = 0; c < 512; c++) a += s1[c] * g_bwt[c*256 + tid];
                     g_ss[b*256 + tid] = a; }
    if (tid < 512) { float a = blb[tid];
                     for (int c = 0; c < 1024; c++) a += s2[c] * g_blwt[c*512 + tid];
                     g_ss2[b*512 + tid] = a; }
}

// ---------------- kernel D: FiLM + all outputs ---------------------------------------
// FiLM index collapse (verified): scale index d' = (d*P + p) mod D
//   D=128, P=256 -> d' = p % 128 ;  D=256, P=256 -> d' = p
__global__ void k_out(float* __restrict__ out, const float* __restrict__ xyz,
                      const int* __restrict__ inds) {
    const int O0 = BB*PP*3;           // 6144
    const int O1 = O0 + BB*128*PP;    // 268288
    const int O2 = O1 + BB*256*PP;    // 792576
    const int O3 = O2 + BB*PP;        // 794624
    int i = blockIdx.x * blockDim.x + threadIdx.x;
    if (i < O0) {
        int b = i / (PP*3); int r = i - b*(PP*3); int p = r/3, d = r - p*3;
        out[i] = xyz[((size_t)b*NN + inds[b*PP + p])*3 + d];
    } else if (i < O1) {
        int j = i - O0;
        int b = j >> 15;            // / (128*256)
        int r = j & 32767;
        int d = r >> 8, p = r & 255;
        int m = p & 127;
        out[i] = g_nf[((b<<8) + p)*128 + d] * (g_ss[b*256 + m] + 1.0f)
               + g_ss[b*256 + 128 + m];
    } else if (i < O2) {
        int j = i - O1;
        int b = j >> 16;            // / (256*256)
        int r = j & 65535;
        int d = r >> 8, p = r & 255;
        out[i] = g_lf[((b<<8) + p)*256 + d] * (g_ss2[b*512 + p] + 1.0f)
               + g_ss2[b*512 + 256 + p];
    } else if (i < O3) {
        out[i] = (float)inds[i - O2];
    }
}

// ---------------- launcher -----------------------------------------------------------
extern "C" void kernel_launch(void* const* d_in, const int* in_sizes, int n_in,
                              void* d_out, int out_size) {
    const float* xyz    = (const float*)d_in[0];
    const float* feat   = (const float*)d_in[1];
    const float* bsize  = (const float*)d_in[2];
    const float* blabel = (const float*)d_in[3];
    const float* ts     = (const float*)d_in[4];
    const int*   inds   = (const int*)  d_in[5];
    const float* mw0 = (const float*)d_in[6],  *mb0 = (const float*)d_in[7];
    const float* mw1 = (const float*)d_in[8],  *mb1 = (const float*)d_in[9];
    const float* mw2 = (const float*)d_in[10], *mb2 = (const float*)d_in[11];
    const float* lw0 = (const float*)d_in[12], *lb0 = (const float*)d_in[13];
    const float* lw1 = (const float*)d_in[14], *lb1 = (const float*)d_in[15];
    const float* lw2 = (const float*)d_in[16], *lb2 = (const float*)d_in[17];
    const float* tw0 = (const float*)d_in[18], *tb0 = (const float*)d_in[19];
    const float* tw1 = (const float*)d_in[20], *tb1 = (const float*)d_in[21];
    const float* bw  = (const float*)d_in[22], *bbv = (const float*)d_in[23];
    const float* tlw0= (const float*)d_in[24], *tlb0= (const float*)d_in[25];
    const float* tlw1= (const float*)d_in[26], *tlb1= (const float*)d_in[27];
    const float* blw = (const float*)d_in[28], *blb = (const float*)d_in[29];
    float* out = (float*)d_out;

    // weight transposes (coalesced one side, tiny)
    auto tl = [](const float* src, int O, int K, int id) {
        k_transpose<<<(O*K + 255)/256, 256>>>(src, O, K, id);
    };
    tl(mw0, 128, 259, 0);
    tl(mw1, 128, 128, 1);
    tl(mw2, 128, 128, 2);
    tl(lw0, 256, 146, 3);
    tl(lw1, 256, 256, 4);
    tl(lw2, 256, 256, 5);
    tl(tw0, 512, 128, 6);
    tl(tw1, 512, 512, 7);
    tl(bw,  256, 512, 8);
    tl(tlw0, 1024, 256, 9);
    tl(tlw1, 1024, 1024, 10);
    tl(blw,  512, 1024, 11);

    k_sample<<<BP/8, 256>>>(xyz, bsize, inds);
    k_time<<<BB, 1024>>>(ts, tb0, tb1, bbv, tlb0, tlb1, blb);

    int smem_b = (32*GST + 2*32*HST) * (int)sizeof(float);   // 67712 B
    cudaFuncSetAttribute(k_mlp, cudaFuncAttributeMaxDynamicSharedMemorySize, smem_b);
    k_mlp<<<BP, 256, smem_b>>>(xyz, feat, inds, mb0, mb1, mb2);

    k_label<<<BP, 256>>>(blabel, lb0, lb1, lb2);

    const int total = BB*PP*3 + BB*128*PP + BB*256*PP + BB*PP;  // 794624
    k_out<<<(total + 255)/256, 256>>>(out, xyz, inds);
}